// round 15
// baseline (speedup 1.0000x reference)
#include <cuda_runtime.h>
#include <cuda_bf16.h>

#define NN 50000
#define NE 800000
#define DD 64

// Scratch (static device globals; zero-initialized at module load).
// INVARIANT: g_neigh is all-zeros at entry of every kernel_launch
// (k_mlp re-zeros its tile after consuming it).
__device__ float g_neigh[NN * DD];
__device__ float g_z2[NN * DD];
__device__ float g_sum[DD];
__device__ float g_sqs[DD];

// ---------------------------------------------------------------------------
// K1: scatter-add  neigh[dst] += h[src]  (16 lanes/edge, RED.v4, int32 idx)
//     block 0 additionally zeros the BN stat accumulators (runs before k_mlp)
// ---------------------------------------------------------------------------
__global__ void k_scatter(const float4* __restrict__ h4,
                          const int* __restrict__ src,
                          const int* __restrict__ dst) {
    if (blockIdx.x == 0 && threadIdx.x < DD) {
        g_sum[threadIdx.x] = 0.f;
        g_sqs[threadIdx.x] = 0.f;
    }
    int t = blockIdx.x * blockDim.x + threadIdx.x;
    int e = t >> 4;
    int part = t & 15;
    if (e >= NE) return;
    int s = src[e];
    int d = dst[e];
    float4 v = __ldg(&h4[(size_t)s * 16 + part]);
    float* p = &g_neigh[(size_t)d * DD + part * 4];
    asm volatile("red.global.add.v4.f32 [%0], {%1,%2,%3,%4};"
                 :: "l"(p), "f"(v.x), "f"(v.y), "f"(v.z), "f"(v.w)
                 : "memory");
}

// ---------------------------------------------------------------------------
// tf32 helpers + swizzled smem addressing
// ---------------------------------------------------------------------------
__device__ __forceinline__ unsigned f2tf(float x) {
    unsigned r;
    asm("cvt.rna.tf32.f32 %0, %1;" : "=r"(r) : "f"(x));
    return r;
}
__device__ __forceinline__ int zidx(int r, int c) {
    return r * DD + (((((c >> 2) ^ (r & 7))) << 2) | (c & 3));
}
__device__ __forceinline__ int wpidx(int k, int n) {
    int kp = ((k >> 3) << 2) + (k & 3);
    int nsw = n ^ ((k & 3) << 2);
    return kp * 128 + nsw * 2 + ((k >> 2) & 1);
}

__device__ __forceinline__ void mma_tf32(float c[4], unsigned a0, unsigned a1,
                                         unsigned a2, unsigned a3,
                                         unsigned b0, unsigned b1) {
    asm volatile(
        "mma.sync.aligned.m16n8k8.row.col.f32.tf32.tf32.f32 "
        "{%0,%1,%2,%3}, {%4,%5,%6,%7}, {%8,%9}, {%0,%1,%2,%3};"
        : "+f"(c[0]), "+f"(c[1]), "+f"(c[2]), "+f"(c[3])
        : "r"(a0), "r"(a1), "r"(a2), "r"(a3), "r"(b0), "r"(b1));
}

// ---------------------------------------------------------------------------
// K2: tf32 MLP. 64 nodes/block, 256 thr (8 warps).
//     warp w: row strip (w&3)*16.., col half (w>>2)*32.. -> acc[4][4].
//     z = h + neigh computed at tile load; g_neigh tile re-zeroed after read.
// ---------------------------------------------------------------------------
__global__ void __launch_bounds__(256) k_mlp(const float4* __restrict__ h4,
                                             const float* __restrict__ W1,
                                             const float* __restrict__ b1,
                                             const float* __restrict__ W2,
                                             const float* __restrict__ b2) {
    __shared__ float sZ[64 * DD];     // 16 KB, swizzled tf32
    __shared__ float sW1f[DD * DD];   // 16 KB, paired float2 tf32
    __shared__ float sW2f[DD * DD];   // 16 KB, paired float2 tf32

    const int tid = threadIdx.x;
    const int node0 = blockIdx.x * 64;
    const int nvalid = min(64, NN - node0);

    // load tile: z = h + neigh (cvt to tf32, swizzled), re-zero g_neigh tile
    for (int i = tid; i < 64 * 16; i += 256) {
        int nd = i >> 4, p = i & 15;
        float4 v = make_float4(0.f, 0.f, 0.f, 0.f);
        if (i < nvalid * 16) {
            float4 a = ((const float4*)g_neigh)[node0 * 16 + i];
            float4 b = __ldg(&h4[node0 * 16 + i]);
            v.x = a.x + b.x; v.y = a.y + b.y;
            v.z = a.z + b.z; v.w = a.w + b.w;
            ((float4*)g_neigh)[node0 * 16 + i] = make_float4(0.f, 0.f, 0.f, 0.f);
        }
        v.x = __uint_as_float(f2tf(v.x));
        v.y = __uint_as_float(f2tf(v.y));
        v.z = __uint_as_float(f2tf(v.z));
        v.w = __uint_as_float(f2tf(v.w));
        *(float4*)&sZ[nd * DD + ((p ^ (nd & 7)) << 2)] = v;
    }
    // load both weight matrices
    for (int i = tid * 4; i < DD * DD; i += 256 * 4) {
        float4 w1 = *(const float4*)&W1[i];
        float4 w2 = *(const float4*)&W2[i];
        int k = i >> 6, n = i & 63;
        sW1f[wpidx(k, n)]     = __uint_as_float(f2tf(w1.x));
        sW1f[wpidx(k, n + 1)] = __uint_as_float(f2tf(w1.y));
        sW1f[wpidx(k, n + 2)] = __uint_as_float(f2tf(w1.z));
        sW1f[wpidx(k, n + 3)] = __uint_as_float(f2tf(w1.w));
        sW2f[wpidx(k, n)]     = __uint_as_float(f2tf(w2.x));
        sW2f[wpidx(k, n + 1)] = __uint_as_float(f2tf(w2.y));
        sW2f[wpidx(k, n + 2)] = __uint_as_float(f2tf(w2.z));
        sW2f[wpidx(k, n + 3)] = __uint_as_float(f2tf(w2.w));
    }
    __syncthreads();

    const int warp = tid >> 5, lane = tid & 31;
    const int qid = lane >> 2;          // 0..7
    const int qtid = lane & 3;          // 0..3
    const int strip = warp & 3;
    const int cbase = (warp >> 2) * 32; // col half
    const int r0 = strip * 16 + qid;
    const float2* sW21 = (const float2*)sW1f;
    const float2* sW22 = (const float2*)sW2f;

    float acc[4][4];
    #pragma unroll
    for (int nt = 0; nt < 4; nt++) {
        int cc = cbase + nt * 8 + 2 * qtid;
        float bb0 = __ldg(&b1[cc]), bb1 = __ldg(&b1[cc + 1]);
        acc[nt][0] = bb0; acc[nt][1] = bb1; acc[nt][2] = bb0; acc[nt][3] = bb1;
    }

    // ---- layer 1 ----
    #pragma unroll
    for (int ks = 0; ks < 8; ks++) {
        int kc = ks * 8 + qtid;
        unsigned a0 = __float_as_uint(sZ[zidx(r0,     kc)]);
        unsigned a1 = __float_as_uint(sZ[zidx(r0 + 8, kc)]);
        unsigned a2 = __float_as_uint(sZ[zidx(r0,     kc + 4)]);
        unsigned a3 = __float_as_uint(sZ[zidx(r0 + 8, kc + 4)]);
        int kp = ks * 4 + qtid;
        #pragma unroll
        for (int nt = 0; nt < 4; nt++) {
            int nsw = (cbase + nt * 8 + qid) ^ (qtid << 2);
            float2 b = sW21[kp * 64 + nsw];
            mma_tf32(acc[nt], a0, a1, a2, a3,
                     __float_as_uint(b.x), __float_as_uint(b.y));
        }
    }
    __syncthreads();   // ALL warps done reading z before anyone overwrites sZ

    // relu + cvt writeback (own cols of own strip)
    #pragma unroll
    for (int nt = 0; nt < 4; nt++) {
        int cc = cbase + nt * 8 + 2 * qtid;
        float2 v0, v1;
        v0.x = __uint_as_float(f2tf(fmaxf(acc[nt][0], 0.f)));
        v0.y = __uint_as_float(f2tf(fmaxf(acc[nt][1], 0.f)));
        v1.x = __uint_as_float(f2tf(fmaxf(acc[nt][2], 0.f)));
        v1.y = __uint_as_float(f2tf(fmaxf(acc[nt][3], 0.f)));
        *(float2*)&sZ[zidx(r0,     cc)] = v0;
        *(float2*)&sZ[zidx(r0 + 8, cc)] = v1;
    }
    __syncthreads();   // full y1 tile visible

    // ---- layer 2 ----
    #pragma unroll
    for (int nt = 0; nt < 4; nt++) {
        int cc = cbase + nt * 8 + 2 * qtid;
        float bb0 = __ldg(&b2[cc]), bb1 = __ldg(&b2[cc + 1]);
        acc[nt][0] = bb0; acc[nt][1] = bb1; acc[nt][2] = bb0; acc[nt][3] = bb1;
    }
    #pragma unroll
    for (int ks = 0; ks < 8; ks++) {
        int kc = ks * 8 + qtid;
        unsigned a0 = __float_as_uint(sZ[zidx(r0,     kc)]);
        unsigned a1 = __float_as_uint(sZ[zidx(r0 + 8, kc)]);
        unsigned a2 = __float_as_uint(sZ[zidx(r0,     kc + 4)]);
        unsigned a3 = __float_as_uint(sZ[zidx(r0 + 8, kc + 4)]);
        int kp = ks * 4 + qtid;
        #pragma unroll
        for (int nt = 0; nt < 4; nt++) {
            int nsw = (cbase + nt * 8 + qid) ^ (qtid << 2);
            float2 b = sW22[kp * 64 + nsw];
            mma_tf32(acc[nt], a0, a1, a2, a3,
                     __float_as_uint(b.x), __float_as_uint(b.y));
        }
    }
    __syncthreads();   // done with sW1 -> reuse as stat scratch

    // store z2 + BN partials: shfl over qid (xor 4,8,16), scratch, one pass
    const int gr0 = node0 + strip * 16 + qid;
    const int gr1 = gr0 + 8;
    float* sRedS = sW1f;          // [8][64]
    float* sRedQ = sW1f + 512;    // [8][64]
    #pragma unroll
    for (int nt = 0; nt < 4; nt++) {
        int cc = cbase + nt * 8 + 2 * qtid;
        float c0 = acc[nt][0], c1 = acc[nt][1], c2 = acc[nt][2], c3 = acc[nt][3];
        float s0 = 0.f, s1 = 0.f, q0 = 0.f, q1 = 0.f;
        if (gr0 < NN) {
            *(float2*)&g_z2[(size_t)gr0 * DD + cc] = make_float2(c0, c1);
            s0 += c0; s1 += c1; q0 += c0 * c0; q1 += c1 * c1;
        }
        if (gr1 < NN) {
            *(float2*)&g_z2[(size_t)gr1 * DD + cc] = make_float2(c2, c3);
            s0 += c2; s1 += c3; q0 += c2 * c2; q1 += c3 * c3;
        }
        #pragma unroll
        for (int o = 4; o < 32; o <<= 1) {
            s0 += __shfl_xor_sync(0xffffffffu, s0, o);
            s1 += __shfl_xor_sync(0xffffffffu, s1, o);
            q0 += __shfl_xor_sync(0xffffffffu, q0, o);
            q1 += __shfl_xor_sync(0xffffffffu, q1, o);
        }
        if (qid == 0) {
            sRedS[warp * 64 + cc]     = s0;
            sRedS[warp * 64 + cc + 1] = s1;
            sRedQ[warp * 64 + cc]     = q0;
            sRedQ[warp * 64 + cc + 1] = q1;
        }
    }
    __syncthreads();
    if (tid < DD) {
        int w0 = (tid >> 5) * 4;    // warps covering this col half
        float S = 0.f, Q = 0.f;
        #pragma unroll
        for (int j = 0; j < 4; j++) {
            S += sRedS[(w0 + j) * 64 + tid];
            Q += sRedQ[(w0 + j) * 64 + tid];
        }
        atomicAdd(&g_sum[tid], S);
        atomicAdd(&g_sqs[tid], Q);
    }
}

// ---------------------------------------------------------------------------
// K3: out = h + relu( z2 * scale + shift )
// ---------------------------------------------------------------------------
__global__ void k_bn(const float4* __restrict__ h4,
                     const float* __restrict__ gamma,
                     const float* __restrict__ beta,
                     float4* __restrict__ out4) {
    __shared__ float sA[DD], sB[DD];
    if (threadIdx.x < DD) {
        const float invN = 1.0f / (float)NN;
        float m = g_sum[threadIdx.x] * invN;
        float v = g_sqs[threadIdx.x] * invN - m * m;
        float a = gamma[threadIdx.x] * rsqrtf(v + 1e-5f);
        sA[threadIdx.x] = a;
        sB[threadIdx.x] = beta[threadIdx.x] - m * a;
    }
    __syncthreads();
    int i = blockIdx.x * blockDim.x + threadIdx.x;
    if (i < NN * 16) {
        float4 z = ((const float4*)g_z2)[i];
        float4 hv = h4[i];
        int dg = (i & 15) * 4;
        float4 o;
        o.x = hv.x + fmaxf(fmaf(z.x, sA[dg + 0], sB[dg + 0]), 0.f);
        o.y = hv.y + fmaxf(fmaf(z.y, sA[dg + 1], sB[dg + 1]), 0.f);
        o.z = hv.z + fmaxf(fmaf(z.z, sA[dg + 2], sB[dg + 2]), 0.f);
        o.w = hv.w + fmaxf(fmaf(z.w, sA[dg + 3], sB[dg + 3]), 0.f);
        out4[i] = o;
    }
}

// ---------------------------------------------------------------------------
extern "C" void kernel_launch(void* const* d_in, const int* in_sizes, int n_in,
                              void* d_out, int out_size) {
    const float* h     = (const float*)d_in[0];
    const float* W1    = (const float*)d_in[1];
    const float* b1    = (const float*)d_in[2];
    const float* W2    = (const float*)d_in[3];
    const float* b2    = (const float*)d_in[4];
    const float* gamma = (const float*)d_in[5];
    const float* beta  = (const float*)d_in[6];
    const int* src     = (const int*)d_in[7];
    const int* dst     = (const int*)d_in[8];

    (void)in_sizes; (void)n_in; (void)out_size;

    k_scatter<<<(NE * 16 + 255) / 256, 256>>>((const float4*)h, src, dst);
    k_mlp<<<(NN + 63) / 64, 256>>>((const float4*)h, W1, b1, W2, b2);
    k_bn<<<(NN * 16 + 255) / 256, 256>>>((const float4*)h, gamma, beta, (float4*)d_out);
}

// round 17
// speedup vs baseline: 1.2596x; 1.2596x over previous
#include <cuda_runtime.h>
#include <cuda_bf16.h>

#define NN 50000
#define NE 800000
#define DD 64

// Scratch (static device globals; zero-initialized at module load).
// INVARIANT: g_neigh is all-zeros at entry of every kernel_launch.
// k_bn (the LAST kernel) restores the zeros, so they are L2-hot when the
// next replay's k_scatter REDs into them.
__device__ float g_neigh[NN * DD];
__device__ float g_z2[NN * DD];
__device__ float g_sum[DD];
__device__ float g_sqs[DD];

// ---------------------------------------------------------------------------
// K1: scatter-add  neigh[dst] += h[src]  (16 lanes/edge, RED.v4, int32 idx)
//     block 0 additionally zeros the BN stat accumulators (done before k_mlp)
// ---------------------------------------------------------------------------
__global__ void k_scatter(const float4* __restrict__ h4,
                          const int* __restrict__ src,
                          const int* __restrict__ dst) {
    if (blockIdx.x == 0 && threadIdx.x < DD) {
        g_sum[threadIdx.x] = 0.f;
        g_sqs[threadIdx.x] = 0.f;
    }
    int t = blockIdx.x * blockDim.x + threadIdx.x;
    int e = t >> 4;
    int part = t & 15;
    if (e >= NE) return;
    int s = src[e];
    int d = dst[e];
    float4 v = __ldg(&h4[(size_t)s * 16 + part]);
    float* p = &g_neigh[(size_t)d * DD + part * 4];
    asm volatile("red.global.add.v4.f32 [%0], {%1,%2,%3,%4};"
                 :: "l"(p), "f"(v.x), "f"(v.y), "f"(v.z), "f"(v.w)
                 : "memory");
}

// ---------------------------------------------------------------------------
// tf32 helpers + swizzled smem addressing
// ---------------------------------------------------------------------------
__device__ __forceinline__ unsigned f2tf(float x) {
    unsigned r;
    asm("cvt.rna.tf32.f32 %0, %1;" : "=r"(r) : "f"(x));
    return r;
}
__device__ __forceinline__ int zidx(int r, int c) {
    return r * DD + (((((c >> 2) ^ (r & 7))) << 2) | (c & 3));
}
__device__ __forceinline__ int wpidx(int k, int n) {
    int kp = ((k >> 3) << 2) + (k & 3);
    int nsw = n ^ ((k & 3) << 2);
    return kp * 128 + nsw * 2 + ((k >> 2) & 1);
}

__device__ __forceinline__ void mma_tf32(float c[4], unsigned a0, unsigned a1,
                                         unsigned a2, unsigned a3,
                                         unsigned b0, unsigned b1) {
    asm volatile(
        "mma.sync.aligned.m16n8k8.row.col.f32.tf32.tf32.f32 "
        "{%0,%1,%2,%3}, {%4,%5,%6,%7}, {%8,%9}, {%0,%1,%2,%3};"
        : "+f"(c[0]), "+f"(c[1]), "+f"(c[2]), "+f"(c[3])
        : "r"(a0), "r"(a1), "r"(a2), "r"(a3), "r"(b0), "r"(b1));
}

// ---------------------------------------------------------------------------
// K2: tf32 MLP. 64 nodes/block, 256 thr (8 warps).
//     warp w: row strip (w&3)*16.., col half (w>>2)*32.. -> acc[4][4].
//     z = h + neigh computed at tile load (eps=0). No writes to g_neigh.
// ---------------------------------------------------------------------------
__global__ void __launch_bounds__(256) k_mlp(const float4* __restrict__ h4,
                                             const float* __restrict__ W1,
                                             const float* __restrict__ b1,
                                             const float* __restrict__ W2,
                                             const float* __restrict__ b2) {
    __shared__ float sZ[64 * DD];     // 16 KB, swizzled tf32
    __shared__ float sW1f[DD * DD];   // 16 KB, paired float2 tf32
    __shared__ float sW2f[DD * DD];   // 16 KB, paired float2 tf32

    const int tid = threadIdx.x;
    const int node0 = blockIdx.x * 64;
    const int nvalid = min(64, NN - node0);

    // load tile: z = h + neigh (cvt to tf32, swizzled); zero-fill tail rows
    for (int i = tid; i < 64 * 16; i += 256) {
        int nd = i >> 4, p = i & 15;
        float4 v = make_float4(0.f, 0.f, 0.f, 0.f);
        if (i < nvalid * 16) {
            float4 a = ((const float4*)g_neigh)[node0 * 16 + i];
            float4 b = __ldg(&h4[node0 * 16 + i]);
            v.x = a.x + b.x; v.y = a.y + b.y;
            v.z = a.z + b.z; v.w = a.w + b.w;
        }
        v.x = __uint_as_float(f2tf(v.x));
        v.y = __uint_as_float(f2tf(v.y));
        v.z = __uint_as_float(f2tf(v.z));
        v.w = __uint_as_float(f2tf(v.w));
        *(float4*)&sZ[nd * DD + ((p ^ (nd & 7)) << 2)] = v;
    }
    // load both weight matrices
    for (int i = tid * 4; i < DD * DD; i += 256 * 4) {
        float4 w1 = *(const float4*)&W1[i];
        float4 w2 = *(const float4*)&W2[i];
        int k = i >> 6, n = i & 63;
        sW1f[wpidx(k, n)]     = __uint_as_float(f2tf(w1.x));
        sW1f[wpidx(k, n + 1)] = __uint_as_float(f2tf(w1.y));
        sW1f[wpidx(k, n + 2)] = __uint_as_float(f2tf(w1.z));
        sW1f[wpidx(k, n + 3)] = __uint_as_float(f2tf(w1.w));
        sW2f[wpidx(k, n)]     = __uint_as_float(f2tf(w2.x));
        sW2f[wpidx(k, n + 1)] = __uint_as_float(f2tf(w2.y));
        sW2f[wpidx(k, n + 2)] = __uint_as_float(f2tf(w2.z));
        sW2f[wpidx(k, n + 3)] = __uint_as_float(f2tf(w2.w));
    }
    __syncthreads();

    const int warp = tid >> 5, lane = tid & 31;
    const int qid = lane >> 2;          // 0..7
    const int qtid = lane & 3;          // 0..3
    const int strip = warp & 3;
    const int cbase = (warp >> 2) * 32; // col half
    const int r0 = strip * 16 + qid;
    const float2* sW21 = (const float2*)sW1f;
    const float2* sW22 = (const float2*)sW2f;

    float acc[4][4];
    #pragma unroll
    for (int nt = 0; nt < 4; nt++) {
        int cc = cbase + nt * 8 + 2 * qtid;
        float bb0 = __ldg(&b1[cc]), bb1 = __ldg(&b1[cc + 1]);
        acc[nt][0] = bb0; acc[nt][1] = bb1; acc[nt][2] = bb0; acc[nt][3] = bb1;
    }

    // ---- layer 1 ----
    #pragma unroll
    for (int ks = 0; ks < 8; ks++) {
        int kc = ks * 8 + qtid;
        unsigned a0 = __float_as_uint(sZ[zidx(r0,     kc)]);
        unsigned a1 = __float_as_uint(sZ[zidx(r0 + 8, kc)]);
        unsigned a2 = __float_as_uint(sZ[zidx(r0,     kc + 4)]);
        unsigned a3 = __float_as_uint(sZ[zidx(r0 + 8, kc + 4)]);
        int kp = ks * 4 + qtid;
        #pragma unroll
        for (int nt = 0; nt < 4; nt++) {
            int nsw = (cbase + nt * 8 + qid) ^ (qtid << 2);
            float2 b = sW21[kp * 64 + nsw];
            mma_tf32(acc[nt], a0, a1, a2, a3,
                     __float_as_uint(b.x), __float_as_uint(b.y));
        }
    }
    __syncthreads();   // ALL warps done reading z before anyone overwrites sZ

    // relu + cvt writeback (own cols of own strip)
    #pragma unroll
    for (int nt = 0; nt < 4; nt++) {
        int cc = cbase + nt * 8 + 2 * qtid;
        float2 v0, v1;
        v0.x = __uint_as_float(f2tf(fmaxf(acc[nt][0], 0.f)));
        v0.y = __uint_as_float(f2tf(fmaxf(acc[nt][1], 0.f)));
        v1.x = __uint_as_float(f2tf(fmaxf(acc[nt][2], 0.f)));
        v1.y = __uint_as_float(f2tf(fmaxf(acc[nt][3], 0.f)));
        *(float2*)&sZ[zidx(r0,     cc)] = v0;
        *(float2*)&sZ[zidx(r0 + 8, cc)] = v1;
    }
    __syncthreads();   // full y1 tile visible

    // ---- layer 2 ----
    #pragma unroll
    for (int nt = 0; nt < 4; nt++) {
        int cc = cbase + nt * 8 + 2 * qtid;
        float bb0 = __ldg(&b2[cc]), bb1 = __ldg(&b2[cc + 1]);
        acc[nt][0] = bb0; acc[nt][1] = bb1; acc[nt][2] = bb0; acc[nt][3] = bb1;
    }
    #pragma unroll
    for (int ks = 0; ks < 8; ks++) {
        int kc = ks * 8 + qtid;
        unsigned a0 = __float_as_uint(sZ[zidx(r0,     kc)]);
        unsigned a1 = __float_as_uint(sZ[zidx(r0 + 8, kc)]);
        unsigned a2 = __float_as_uint(sZ[zidx(r0,     kc + 4)]);
        unsigned a3 = __float_as_uint(sZ[zidx(r0 + 8, kc + 4)]);
        int kp = ks * 4 + qtid;
        #pragma unroll
        for (int nt = 0; nt < 4; nt++) {
            int nsw = (cbase + nt * 8 + qid) ^ (qtid << 2);
            float2 b = sW22[kp * 64 + nsw];
            mma_tf32(acc[nt], a0, a1, a2, a3,
                     __float_as_uint(b.x), __float_as_uint(b.y));
        }
    }
    __syncthreads();   // done with sW1 -> reuse as stat scratch

    // store z2 + BN partials: shfl over qid (xor 4,8,16), scratch, one pass
    const int gr0 = node0 + strip * 16 + qid;
    const int gr1 = gr0 + 8;
    float* sRedS = sW1f;          // [8][64]
    float* sRedQ = sW1f + 512;    // [8][64]
    #pragma unroll
    for (int nt = 0; nt < 4; nt++) {
        int cc = cbase + nt * 8 + 2 * qtid;
        float c0 = acc[nt][0], c1 = acc[nt][1], c2 = acc[nt][2], c3 = acc[nt][3];
        float s0 = 0.f, s1 = 0.f, q0 = 0.f, q1 = 0.f;
        if (gr0 < NN) {
            *(float2*)&g_z2[(size_t)gr0 * DD + cc] = make_float2(c0, c1);
            s0 += c0; s1 += c1; q0 += c0 * c0; q1 += c1 * c1;
        }
        if (gr1 < NN) {
            *(float2*)&g_z2[(size_t)gr1 * DD + cc] = make_float2(c2, c3);
            s0 += c2; s1 += c3; q0 += c2 * c2; q1 += c3 * c3;
        }
        #pragma unroll
        for (int o = 4; o < 32; o <<= 1) {
            s0 += __shfl_xor_sync(0xffffffffu, s0, o);
            s1 += __shfl_xor_sync(0xffffffffu, s1, o);
            q0 += __shfl_xor_sync(0xffffffffu, q0, o);
            q1 += __shfl_xor_sync(0xffffffffu, q1, o);
        }
        if (qid == 0) {
            sRedS[warp * 64 + cc]     = s0;
            sRedS[warp * 64 + cc + 1] = s1;
            sRedQ[warp * 64 + cc]     = q0;
            sRedQ[warp * 64 + cc + 1] = q1;
        }
    }
    __syncthreads();
    if (tid < DD) {
        int w0 = (tid >> 5) * 4;    // warps covering this col half
        float S = 0.f, Q = 0.f;
        #pragma unroll
        for (int j = 0; j < 4; j++) {
            S += sRedS[(w0 + j) * 64 + tid];
            Q += sRedQ[(w0 + j) * 64 + tid];
        }
        atomicAdd(&g_sum[tid], S);
        atomicAdd(&g_sqs[tid], Q);
    }
}

// ---------------------------------------------------------------------------
// K3: out = h + relu( z2 * scale + shift ); also restores g_neigh zeros
//     (last kernel -> zeros are L2-hot for the next replay's scatter)
// ---------------------------------------------------------------------------
__global__ void k_bn(const float4* __restrict__ h4,
                     const float* __restrict__ gamma,
                     const float* __restrict__ beta,
                     float4* __restrict__ out4) {
    __shared__ float sA[DD], sB[DD];
    if (threadIdx.x < DD) {
        const float invN = 1.0f / (float)NN;
        float m = g_sum[threadIdx.x] * invN;
        float v = g_sqs[threadIdx.x] * invN - m * m;
        float a = gamma[threadIdx.x] * rsqrtf(v + 1e-5f);
        sA[threadIdx.x] = a;
        sB[threadIdx.x] = beta[threadIdx.x] - m * a;
    }
    __syncthreads();
    int i = blockIdx.x * blockDim.x + threadIdx.x;
    if (i < NN * 16) {
        float4 z = ((const float4*)g_z2)[i];
        float4 hv = h4[i];
        int dg = (i & 15) * 4;
        float4 o;
        o.x = hv.x + fmaxf(fmaf(z.x, sA[dg + 0], sB[dg + 0]), 0.f);
        o.y = hv.y + fmaxf(fmaf(z.y, sA[dg + 1], sB[dg + 1]), 0.f);
        o.z = hv.z + fmaxf(fmaf(z.z, sA[dg + 2], sB[dg + 2]), 0.f);
        o.w = hv.w + fmaxf(fmaf(z.w, sA[dg + 3], sB[dg + 3]), 0.f);
        out4[i] = o;
        ((float4*)g_neigh)[i] = make_float4(0.f, 0.f, 0.f, 0.f);
    }
}

// ---------------------------------------------------------------------------
extern "C" void kernel_launch(void* const* d_in, const int* in_sizes, int n_in,
                              void* d_out, int out_size) {
    const float* h     = (const float*)d_in[0];
    const float* W1    = (const float*)d_in[1];
    const float* b1    = (const float*)d_in[2];
    const float* W2    = (const float*)d_in[3];
    const float* b2    = (const float*)d_in[4];
    const float* gamma = (const float*)d_in[5];
    const float* beta  = (const float*)d_in[6];
    const int* src     = (const int*)d_in[7];
    const int* dst     = (const int*)d_in[8];

    (void)in_sizes; (void)n_in; (void)out_size;

    k_scatter<<<(NE * 16 + 255) / 256, 256>>>((const float4*)h, src, dst);
    k_mlp<<<(NN + 63) / 64, 256>>>((const float4*)h, W1, b1, W2, b2);
    k_bn<<<(NN * 16 + 255) / 256, 256>>>((const float4*)h, gamma, beta, (float4*)d_out);
}